// round 6
// baseline (speedup 1.0000x reference)
#include <cuda_runtime.h>
#include <cstdint>

#define N_FEAT 512
#define N_PAIRS (N_FEAT * (N_FEAT - 1) / 2)   // 130816
#define TB 8            // batch rows per block
#define THREADS 256
#define PPT 4           // pairs per thread
#define PPB (THREADS * PPT)  // 1024

// 16B-unit swizzle (SW128-style): unit (f, c) lives at sw_unit(2f + c).
// Conflict-free for lane-stride-2-unit LDS.128 / STS.128 patterns.
__device__ __forceinline__ int sw_unit(int raw) {
    return raw ^ ((raw >> 3) & 7);
}

__device__ __forceinline__ int tri_off(int i) {
    return (i * (2 * N_FEAT - 1 - i)) >> 1;
}

__device__ __forceinline__ void pair_from_p(int p, int& i, int& j) {
    float t = (float)N_FEAT - 0.5f;
    float d = t * t - 2.0f * (float)p;
    d = d > 0.0f ? d : 0.0f;
    int ii = (int)floorf(t - sqrtf(d));
    if (ii < 0) ii = 0;
    if (ii > N_FEAT - 2) ii = N_FEAT - 2;
    while (ii < N_FEAT - 2 && tri_off(ii + 1) <= p) ii++;
    while (ii > 0 && tri_off(ii) > p) ii--;
    i = ii;
    j = ii + 1 + (p - tri_off(ii));
}

// scalar accessor for the slow path: value of feature f, local batch row b
__device__ __forceinline__ float xsv(const float4* xs4, int f, int b) {
    return ((const float*)&xs4[sw_unit(2 * f + (b >> 2))])[b & 3];
}

__global__ void __launch_bounds__(THREADS, 6)
wide_layer_kernel(const float* __restrict__ x,
                  const float* __restrict__ w,
                  float* __restrict__ out)
{
    // batch-minor tile: unit (f, c) = x[b0 + 4c + 0..3][f], swizzled. 16 KB.
    __shared__ float4 xs4[N_FEAT * 2];

    const int tid = threadIdx.x;
    const int b0  = blockIdx.y * TB;

    // Fill: each thread packs 4 units. Lanes have consecutive f -> LDG fully
    // coalesced per component; STS.128 conflict-free under the swizzle.
    #pragma unroll
    for (int k = 0; k < (N_FEAT * 2) / THREADS; k++) {
        int idx = k * THREADS + tid;        // 0..1023
        int c   = idx >> 9;                 // half (b 0..3 vs 4..7)
        int f   = idx & (N_FEAT - 1);
        const float* src = x + (size_t)(b0 + 4 * c) * N_FEAT + f;
        float4 v;
        v.x = src[0 * N_FEAT];
        v.y = src[1 * N_FEAT];
        v.z = src[2 * N_FEAT];
        v.w = src[3 * N_FEAT];
        xs4[sw_unit(2 * f + c)] = v;
    }
    __syncthreads();

    const int p0 = blockIdx.x * PPB + tid * PPT;
    if (p0 >= N_PAIRS) return;

    const float4 w4 = *(const float4*)(w + p0);
    float4* dst = (float4*)(out + (size_t)b0 * N_PAIRS + p0);
    const size_t dstride = N_PAIRS / 4;

    int i0, j0;
    pair_from_p(p0, i0, j0);

    if (p0 < N_PAIRS - PPT) {
        // Fast path: the 4 pairs span at most 2 distinct i rows (proven: only
        // the final thread p0 == N_PAIRS-4 spans 3).
        int ia0 = i0, ia3;
        bool s1, s2;
        int u_j0, u_j1, u_j2, u_j3;
        {
            int ii = i0, jj = j0;
            int iarr[PPT], jarr[PPT];
            #pragma unroll
            for (int k = 0; k < PPT; k++) {
                iarr[k] = ii; jarr[k] = jj;
                jj++;
                if (jj == N_FEAT) { ii++; jj = ii + 1; }
            }
            ia3 = iarr[3];
            s1 = (iarr[1] == ia0);
            s2 = (iarr[2] == ia0);
            u_j0 = sw_unit(2 * jarr[0]);
            u_j1 = sw_unit(2 * jarr[1]);
            u_j2 = sw_unit(2 * jarr[2]);
            u_j3 = sw_unit(2 * jarr[3]);
        }
        const int u_ia = sw_unit(2 * ia0);
        const int u_ib = sw_unit(2 * ia3);

        #pragma unroll
        for (int h = 0; h < 2; h++) {
            // raw is even, so unit for c=1 is unit(c=0) ^ 1
            float4 xia = xs4[u_ia ^ h];   // broadcast
            float4 xib = xs4[u_ib ^ h];   // broadcast
            float4 xj0 = xs4[u_j0 ^ h];
            float4 xj1 = xs4[u_j1 ^ h];
            float4 xj2 = xs4[u_j2 ^ h];
            float4 xj3 = xs4[u_j3 ^ h];

            #define DO_ROW(CMP)                                            \
            {                                                              \
                float xi1 = s1 ? xia.CMP : xib.CMP;                        \
                float xi2 = s2 ? xia.CMP : xib.CMP;                        \
                float4 o;                                                  \
                o.x = xia.CMP * xj0.CMP * w4.x;                            \
                o.y = xi1     * xj1.CMP * w4.y;                            \
                o.z = xi2     * xj2.CMP * w4.z;                            \
                o.w = xib.CMP * xj3.CMP * w4.w;                            \
                __stcs(dst, o);                                            \
                dst += dstride;                                            \
            }
            DO_ROW(x) DO_ROW(y) DO_ROW(z) DO_ROW(w)
            #undef DO_ROW
        }
    } else {
        // Slow path: exactly one thread (last 4 pairs, spans rows 508/509/510)
        int ii = i0, jj = j0;
        #pragma unroll
        for (int k = 0; k < PPT; k++) {
            float wk = ((const float*)&w4)[k];
            for (int b = 0; b < TB; b++) {
                out[(size_t)(b0 + b) * N_PAIRS + p0 + k] =
                    xsv(xs4, ii, b) * xsv(xs4, jj, b) * wk;
            }
            jj++;
            if (jj == N_FEAT) { ii++; jj = ii + 1; }
        }
    }
}

extern "C" void kernel_launch(void* const* d_in, const int* in_sizes, int n_in,
                              void* d_out, int out_size)
{
    const float* x = (const float*)d_in[0];
    const float* w = (const float*)d_in[1];
    float* out = (float*)d_out;

    dim3 grid((N_PAIRS + PPB - 1) / PPB, 1024 / TB);
    wide_layer_kernel<<<grid, THREADS>>>(x, w, out);
}

// round 7
// speedup vs baseline: 1.0346x; 1.0346x over previous
#include <cuda_runtime.h>
#include <cstdint>

#define N_FEAT 512
#define N_PAIRS (N_FEAT * (N_FEAT - 1) / 2)   // 130816
#define TB 16           // batch rows per block
#define THREADS 256
#define PPT 4           // pairs per thread
#define PPB (THREADS * PPT)  // 1024

// Bank-permutation: feature f stored at word perm(f).
// For lane-stride-4 access (j = j0 + 4*lane), perm(j) mod 32 strides 1 -> conflict-free.
__device__ __forceinline__ int perm(int f) {
    return (f >> 2) | ((f & 3) << 7);
}

__device__ __forceinline__ int tri_off(int i) {
    return (i * (2 * N_FEAT - 1 - i)) >> 1;
}

__device__ __forceinline__ void pair_from_p(int p, int& i, int& j) {
    float t = (float)N_FEAT - 0.5f;
    float d = t * t - 2.0f * (float)p;
    d = d > 0.0f ? d : 0.0f;
    int ii = (int)floorf(t - sqrtf(d));
    if (ii < 0) ii = 0;
    if (ii > N_FEAT - 2) ii = N_FEAT - 2;
    while (ii < N_FEAT - 2 && tri_off(ii + 1) <= p) ii++;
    while (ii > 0 && tri_off(ii) > p) ii--;
    i = ii;
    j = ii + 1 + (p - tri_off(ii));
}

__global__ void __launch_bounds__(THREADS, 6)
wide_layer_kernel(const float* __restrict__ x,
                  const float* __restrict__ w,
                  float* __restrict__ out)
{
    __shared__ float xs[TB * N_FEAT];   // 32 KB, bank-permuted per row

    const int tid = threadIdx.x;
    const int b0  = blockIdx.y * TB;

    // Cooperative fill into the permuted layout.
    // Per STS instruction lanes hit bank-stride-1 -> conflict-free.
    {
        const float4* xg = (const float4*)(x + (size_t)b0 * N_FEAT);
        #pragma unroll
        for (int k = 0; k < (TB * N_FEAT / 4) / THREADS; k++) {
            int v = tid + k * THREADS;          // float4 index within tile
            int row = v >> 7;                   // / (N_FEAT/4)
            int c   = v & 127;
            float4 val = xg[v];
            float* dstp = xs + row * N_FEAT;
            int f = c * 4;
            dstp[perm(f + 0)] = val.x;
            dstp[perm(f + 1)] = val.y;
            dstp[perm(f + 2)] = val.z;
            dstp[perm(f + 3)] = val.w;
        }
    }
    __syncthreads();

    const int p0 = blockIdx.x * PPB + tid * PPT;
    if (p0 >= N_PAIRS) return;

    // per-thread pair plan (pre-permuted smem indices)
    int ip0, ipb, ip1, ip2;
    int jp[PPT];
    bool s1, s2, odd1, odd2, same;
    {
        int ii, jj;
        pair_from_p(p0, ii, jj);
        int iarr[PPT];
        #pragma unroll
        for (int k = 0; k < PPT; k++) {
            iarr[k] = ii;
            jp[k] = perm(jj);
            jj++;
            if (jj == N_FEAT) { ii++; jj = ii + 1; }
        }
        ip0  = perm(iarr[0]);
        ip1  = perm(iarr[1]);
        ip2  = perm(iarr[2]);
        ipb  = perm(iarr[3]);
        same = (iarr[3] == iarr[0]);                          // quad in one i row
        s1   = (iarr[1] == iarr[0]);
        s2   = (iarr[2] == iarr[0]);
        odd1 = (iarr[1] != iarr[0]) && (iarr[1] != iarr[3]);  // 3-row span (rare)
        odd2 = (iarr[2] != iarr[0]) && (iarr[2] != iarr[3]);
    }

    const float4 w4 = *(const float4*)(w + p0);

    float4* dst = (float4*)(out + (size_t)b0 * N_PAIRS + p0);
    const size_t dstride = N_PAIRS / 4;

    const float* xr = xs;
    #pragma unroll
    for (int b = 0; b < TB; b++) {
        float xia = xr[ip0];                  // broadcast LDS (1 wf)
        float xib = xia;
        if (!same) xib = xr[ipb];             // predicated: 0 wf in clean warps
        float x1 = s1 ? xia : xib;
        float x2 = s2 ? xia : xib;
        if (odd1) x1 = xr[ip1];               // rare fixup (1 thread / batch group)
        if (odd2) x2 = xr[ip2];
        float4 o;
        o.x = xia * xr[jp[0]] * w4.x;
        o.y = x1  * xr[jp[1]] * w4.y;
        o.z = x2  * xr[jp[2]] * w4.z;
        o.w = xib * xr[jp[3]] * w4.w;
        __stcs(dst, o);
        dst += dstride;
        xr  += N_FEAT;
    }
}

extern "C" void kernel_launch(void* const* d_in, const int* in_sizes, int n_in,
                              void* d_out, int out_size)
{
    const float* x = (const float*)d_in[0];
    const float* w = (const float*)d_in[1];
    float* out = (float*)d_out;

    dim3 grid((N_PAIRS + PPB - 1) / PPB, 1024 / TB);
    wide_layer_kernel<<<grid, THREADS>>>(x, w, out);
}

// round 8
// speedup vs baseline: 1.0652x; 1.0296x over previous
#include <cuda_runtime.h>
#include <cstdint>

#define N_FEAT 512
#define N_PAIRS (N_FEAT * (N_FEAT - 1) / 2)   // 130816 (divisible by 4)
#define TB 8            // batch rows per block
#define THREADS 256
#define PPT 4           // pairs per thread
#define PPB (THREADS * PPT)  // 1024

// Bank-permutation: feature f stored at word perm(f).
// For lane-stride-4 access (j = j0 + 4*lane), perm(j) mod 32 strides 1 -> conflict-free.
__device__ __forceinline__ int perm(int f) {
    return (f >> 2) | ((f & 3) << 7);
}

__device__ __forceinline__ int tri_off(int i) {
    return (i * (2 * N_FEAT - 1 - i)) >> 1;
}

__device__ __forceinline__ void pair_from_p(int p, int& i, int& j) {
    float t = (float)N_FEAT - 0.5f;
    float d = t * t - 2.0f * (float)p;
    d = d > 0.0f ? d : 0.0f;
    int ii = (int)floorf(t - sqrtf(d));
    if (ii < 0) ii = 0;
    if (ii > N_FEAT - 2) ii = N_FEAT - 2;
    while (ii < N_FEAT - 2 && tri_off(ii + 1) <= p) ii++;
    while (ii > 0 && tri_off(ii) > p) ii--;
    i = ii;
    j = ii + 1 + (p - tri_off(ii));
}

__global__ void __launch_bounds__(THREADS, 8)
wide_layer_kernel(const float* __restrict__ x,
                  const float* __restrict__ w,
                  float* __restrict__ out)
{
    __shared__ float xs[TB * N_FEAT];   // 16 KB, bank-permuted per row

    const int tid = threadIdx.x;
    const int b0  = blockIdx.y * TB;

    // Cooperative fill into the permuted layout.
    // Per STS instruction lanes hit bank-stride-1 -> conflict-free.
    {
        const float4* xg = (const float4*)(x + (size_t)b0 * N_FEAT);
        #pragma unroll
        for (int k = 0; k < (TB * N_FEAT / 4) / THREADS; k++) {
            int v = tid + k * THREADS;          // float4 index within tile
            int row = v >> 7;                   // / (N_FEAT/4)
            int c   = v & 127;
            float4 val = xg[v];
            float* dstp = xs + row * N_FEAT;
            int f = c * 4;
            dstp[perm(f + 0)] = val.x;
            dstp[perm(f + 1)] = val.y;
            dstp[perm(f + 2)] = val.z;
            dstp[perm(f + 3)] = val.w;
        }
    }
    __syncthreads();

    const int p0 = blockIdx.x * PPB + tid * PPT;
    if (p0 >= N_PAIRS) return;

    // compute the 4 (i,j) pairs once per thread (pre-permuted smem indices)
    int ip[PPT], jp[PPT];
    {
        int ii, jj;
        pair_from_p(p0, ii, jj);
        #pragma unroll
        for (int k = 0; k < PPT; k++) {
            ip[k] = perm(ii);
            jp[k] = perm(jj);
            jj++;
            if (jj == N_FEAT) { ii++; jj = ii + 1; }
        }
    }

    // i-side selection plan: 4 pairs span at most 2 distinct i values, except
    // one thread per p-block (rows 508/509/510) which gets predicated LDS.
    const bool s1   = (ip[1] == ip[0]);
    const bool s2   = (ip[2] == ip[0]);
    const bool odd1 = (ip[1] != ip[0]) && (ip[1] != ip[3]);  // 3-row span (rare)
    const bool odd2 = (ip[2] != ip[0]) && (ip[2] != ip[3]);

    const float4 w4 = *(const float4*)(w + p0);

    float4* dst = (float4*)(out + (size_t)b0 * N_PAIRS + p0);
    const size_t dstride = N_PAIRS / 4;

    const float* xr = xs;
    #pragma unroll
    for (int b = 0; b < TB; b++) {
        float xia = xr[ip[0]];                // broadcast LDS
        float xib = xr[ip[3]];                // broadcast LDS
        float x1 = s1 ? xia : xib;
        float x2 = s2 ? xia : xib;
        if (odd1) x1 = xr[ip[1]];             // rare fixup (1 thread / p-block)
        if (odd2) x2 = xr[ip[2]];
        float4 o;
        o.x = xia * xr[jp[0]] * w4.x;
        o.y = x1  * xr[jp[1]] * w4.y;
        o.z = x2  * xr[jp[2]] * w4.z;
        o.w = xib * xr[jp[3]] * w4.w;
        __stcs(dst, o);   // streaming store: keep x/w resident in L2
        dst += dstride;
        xr  += N_FEAT;
    }
}

extern "C" void kernel_launch(void* const* d_in, const int* in_sizes, int n_in,
                              void* d_out, int out_size)
{
    const float* x = (const float*)d_in[0];
    const float* w = (const float*)d_in[1];
    float* out = (float*)d_out;

    dim3 grid((N_PAIRS + PPB - 1) / PPB, 1024 / TB);
    wide_layer_kernel<<<grid, THREADS>>>(x, w, out);
}